// round 6
// baseline (speedup 1.0000x reference)
#include <cuda_runtime.h>
#include <math.h>

// Swin block: B=32, H=W=112, C=96, NH=3, WS=7, SHIFT=3
#define B_      32
#define H_      112
#define W_      112
#define C_      96
#define NH_     3
#define WS_     7
#define SHIFT_  3
#define N_      49
#define HD_     32
#define NW_IMG  256
#define NWIN    8192
#define TOK     401408
#define HID_    384
#define PAD_    100          // padded smem row (floats), 16B-aligned

// ---------------- scratch ---------------------------------------------------
__device__ float g_qkv[(size_t)3 * NWIN * NH_ * N_ * HD_];
__device__ float g_ao[(size_t)NWIN * N_ * C_];
__device__ float g_x1[(size_t)TOK * C_];
__device__ float g_h [(size_t)TOK * HID_];

#define QKV_SEG ((size_t)NWIN * NH_ * N_ * HD_)

// ---------------------------------------------------------------------------
// K1: LN1 + shift + window + QKV GEMM (49x96 @ 96x288), 4 col-tiles of 72.
// 256 threads. GEMM: tr=tid%7 (7 rows each), tc=tid/7 (2 cols each), 252 act.
// smem: sx 49*100*4=19600 + swt 72*100*4=28800 = 48400 B
// ---------------------------------------------------------------------------
__global__ __launch_bounds__(256) void k1_ln_qkv(
    const float* __restrict__ x,
    const float* __restrict__ n1g, const float* __restrict__ n1b,
    const float* __restrict__ qkv_w, const float* __restrict__ qkv_b)
{
    __shared__ float sx[N_][PAD_];
    __shared__ float swt[72][PAD_];
    const int win = blockIdx.x;
    const int b = win >> 8;
    const int wi = win & 255;
    const int wh = wi >> 4, ww = wi & 15;
    const int tid = threadIdx.x;
    const int warp = tid >> 5, lane = tid & 31;

    // ---- LN1 -------------------------------------------------------------
    for (int n = warp; n < N_; n += 8) {
        const int i = n / 7, j = n % 7;
        const int sh = (wh * 7 + i + SHIFT_) % H_;
        const int sw = (ww * 7 + j + SHIFT_) % W_;
        const float* row = x + (size_t)(b * H_ * W_ + sh * W_ + sw) * C_;
        float v0 = row[lane], v1 = row[lane + 32], v2 = row[lane + 64];
        float s = v0 + v1 + v2;
        float ss = v0 * v0 + v1 * v1 + v2 * v2;
        #pragma unroll
        for (int o = 16; o > 0; o >>= 1) {
            s  += __shfl_xor_sync(0xffffffffu, s, o);
            ss += __shfl_xor_sync(0xffffffffu, ss, o);
        }
        const float mean = s * (1.f / 96.f);
        const float var  = ss * (1.f / 96.f) - mean * mean;
        const float rstd = rsqrtf(var + 1e-5f);
        sx[n][lane]      = (v0 - mean) * rstd * n1g[lane]      + n1b[lane];
        sx[n][lane + 32] = (v1 - mean) * rstd * n1g[lane + 32] + n1b[lane + 32];
        sx[n][lane + 64] = (v2 - mean) * rstd * n1g[lane + 64] + n1b[lane + 64];
    }
    __syncthreads();

    const int tr = tid % 7;             // row group: rows tr*7 .. tr*7+6
    const int tc = tid / 7;             // col pair:  cols tc*2, tc*2+1
    const bool act = (tid < 252);

    for (int ct = 0; ct < 4; ct++) {
        // stage weight tile col-major: swt[c][k] = qkv_w[(ct*72+c)*96 + k]
        for (int idx = tid; idx < 72 * 24; idx += 256) {
            const int c = idx / 24, kc = idx % 24;
            *(float4*)&swt[c][kc * 4] =
                *(const float4*)&qkv_w[(ct * 72 + c) * C_ + kc * 4];
        }
        __syncthreads();

        if (act) {
            float acc[7][2];
            #pragma unroll
            for (int r = 0; r < 7; r++) { acc[r][0] = 0.f; acc[r][1] = 0.f; }

            #pragma unroll 3
            for (int kc = 0; kc < 24; kc++) {
                float4 w0 = *(const float4*)&swt[tc * 2 + 0][kc * 4];
                float4 w1 = *(const float4*)&swt[tc * 2 + 1][kc * 4];
                #pragma unroll
                for (int r = 0; r < 7; r++) {
                    float4 a = *(const float4*)&sx[tr * 7 + r][kc * 4];
                    acc[r][0] += a.x * w0.x + a.y * w0.y + a.z * w0.z + a.w * w0.w;
                    acc[r][1] += a.x * w1.x + a.y * w1.y + a.z * w1.z + a.w * w1.w;
                }
            }

            #pragma unroll
            for (int c = 0; c < 2; c++) {
                const int col = ct * 72 + tc * 2 + c;
                const int which = col / 96;
                const int head = (col % 96) / 32;
                const int hd = col & 31;
                const float bb = qkv_b[col];
                const float scale = (which == 0) ? 0.17677669529663687f : 1.f;
                float* dst = g_qkv + (size_t)which * QKV_SEG;
                const size_t base = ((size_t)win * NH_ + head) * N_ * HD_ + hd;
                #pragma unroll
                for (int r = 0; r < 7; r++)
                    dst[base + (size_t)(tr * 7 + r) * HD_] = (acc[r][c] + bb) * scale;
            }
        }
        __syncthreads();
    }
}

// ---------------------------------------------------------------------------
// K2: attention per (window, head). 64 threads; thread i = query row i.
// ---------------------------------------------------------------------------
__global__ __launch_bounds__(64) void k2_attn(
    const float* __restrict__ attn_mask,
    const int* __restrict__ rel_index,
    const float* __restrict__ rel_tab)
{
    __shared__ float sk[N_][HD_];
    __shared__ float sv[N_][HD_];
    __shared__ float sbm[N_][N_];
    const int win = blockIdx.x;
    const int head = blockIdx.y;
    const int tid = threadIdx.x;

    const float* kp = g_qkv + QKV_SEG + ((size_t)win * NH_ + head) * N_ * HD_;
    const float* vp = g_qkv + 2 * QKV_SEG + ((size_t)win * NH_ + head) * N_ * HD_;
    for (int i = tid; i < N_ * HD_ / 4; i += 64) {
        ((float4*)&sk[0][0])[i] = ((const float4*)kp)[i];
        ((float4*)&sv[0][0])[i] = ((const float4*)vp)[i];
    }
    const float* mp = attn_mask + (size_t)(win & 255) * N_ * N_;
    for (int i = tid; i < N_ * N_; i += 64)
        (&sbm[0][0])[i] = rel_tab[rel_index[i] * NH_ + head] + mp[i];
    __syncthreads();

    if (tid >= N_) return;
    const float* qp = g_qkv + (((size_t)win * NH_ + head) * N_ + tid) * HD_;
    float q[HD_];
    #pragma unroll
    for (int d = 0; d < HD_; d += 4) {
        float4 qq = *(const float4*)&qp[d];
        q[d] = qq.x; q[d+1] = qq.y; q[d+2] = qq.z; q[d+3] = qq.w;
    }

    float s[N_];
    float mx = -1e30f;
    #pragma unroll
    for (int j = 0; j < N_; j++) {
        float acc = sbm[tid][j];
        #pragma unroll
        for (int d = 0; d < HD_; d++) acc += q[d] * sk[j][d];
        s[j] = acc;
        mx = fmaxf(mx, acc);
    }
    float denom = 0.f;
    #pragma unroll
    for (int j = 0; j < N_; j++) { s[j] = __expf(s[j] - mx); denom += s[j]; }
    const float inv = 1.f / denom;

    float o[HD_];
    #pragma unroll
    for (int d = 0; d < HD_; d++) o[d] = 0.f;
    #pragma unroll
    for (int j = 0; j < N_; j++) {
        const float p = s[j];
        #pragma unroll
        for (int d = 0; d < HD_; d++) o[d] += p * sv[j][d];
    }
    float* op = g_ao + ((size_t)win * N_ + tid) * C_ + head * HD_;
    #pragma unroll
    for (int d = 0; d < HD_; d++) op[d] = o[d] * inv;
}

// ---------------------------------------------------------------------------
// K3: proj (49x96 @ 96x96) + reverse + unshift + residual. 2 col-tiles of 48.
// 192 threads. tr=tid%7, tc=tid/7 (2 cols), 168 active.
// smem: sa 19600 + swt 48*100*4=19200 = 38800 B
// ---------------------------------------------------------------------------
__global__ __launch_bounds__(192) void k3_proj(
    const float* __restrict__ x,
    const float* __restrict__ proj_w, const float* __restrict__ proj_b)
{
    __shared__ float sa[N_][PAD_];
    __shared__ float swt[48][PAD_];
    const int win = blockIdx.x;
    const int b = win >> 8;
    const int wi = win & 255;
    const int wh = wi >> 4, ww = wi & 15;
    const int tid = threadIdx.x;

    const float* ap = g_ao + (size_t)win * N_ * C_;
    for (int idx = tid; idx < N_ * 24; idx += 192) {
        const int n = idx / 24, kc = idx % 24;
        *(float4*)&sa[n][kc * 4] = *(const float4*)&ap[n * C_ + kc * 4];
    }
    __syncthreads();

    const int tr = tid % 7;
    const int tc = tid / 7;
    const bool act = (tid < 168);

    for (int ct = 0; ct < 2; ct++) {
        for (int idx = tid; idx < 48 * 24; idx += 192) {
            const int c = idx / 24, kc = idx % 24;
            *(float4*)&swt[c][kc * 4] =
                *(const float4*)&proj_w[(ct * 48 + c) * C_ + kc * 4];
        }
        __syncthreads();

        if (act) {
            float acc[7][2];
            #pragma unroll
            for (int r = 0; r < 7; r++) { acc[r][0] = 0.f; acc[r][1] = 0.f; }

            #pragma unroll 3
            for (int kc = 0; kc < 24; kc++) {
                float4 w0 = *(const float4*)&swt[tc * 2 + 0][kc * 4];
                float4 w1 = *(const float4*)&swt[tc * 2 + 1][kc * 4];
                #pragma unroll
                for (int r = 0; r < 7; r++) {
                    float4 a = *(const float4*)&sa[tr * 7 + r][kc * 4];
                    acc[r][0] += a.x * w0.x + a.y * w0.y + a.z * w0.z + a.w * w0.w;
                    acc[r][1] += a.x * w1.x + a.y * w1.y + a.z * w1.z + a.w * w1.w;
                }
            }

            #pragma unroll
            for (int r = 0; r < 7; r++) {
                const int n = tr * 7 + r;
                const int i = n / 7, j = n % 7;
                const int sh = (wh * 7 + i + SHIFT_) % H_;
                const int sw = (ww * 7 + j + SHIFT_) % W_;
                const size_t tok = (size_t)(b * H_ * W_ + sh * W_ + sw);
                const int col = ct * 48 + tc * 2;
                float2 xr = *(const float2*)&x[tok * C_ + col];
                float2 o;
                o.x = xr.x + acc[r][0] + proj_b[col + 0];
                o.y = xr.y + acc[r][1] + proj_b[col + 1];
                *(float2*)&g_x1[tok * C_ + col] = o;
            }
        }
        __syncthreads();
    }
}

// ---------------------------------------------------------------------------
// K4a: LN2 + FC1 + GELU -> g_h. 64 tokens/block, 256 threads, 8 tiles of 48.
// rg=tid/16 (4 rows), cg=tid%16 (3 cols).
// smem: sxn 64*96*4=24576 + swt 48*100*4=19200 = 43776 B
// ---------------------------------------------------------------------------
__global__ __launch_bounds__(256) void k4a_fc1(
    const float* __restrict__ n2g, const float* __restrict__ n2b,
    const float* __restrict__ f1w, const float* __restrict__ f1b)
{
    __shared__ float sxn[64][C_];
    __shared__ float swt[48][PAD_];
    const int t0 = blockIdx.x * 64;
    const int tid = threadIdx.x;
    const int warp = tid >> 5, lane = tid & 31;

    // ---- LN2 -------------------------------------------------------------
    for (int t = warp; t < 64; t += 8) {
        const float* row = g_x1 + (size_t)(t0 + t) * C_;
        float v0 = row[lane], v1 = row[lane + 32], v2 = row[lane + 64];
        float s = v0 + v1 + v2;
        float ss = v0 * v0 + v1 * v1 + v2 * v2;
        #pragma unroll
        for (int o = 16; o > 0; o >>= 1) {
            s  += __shfl_xor_sync(0xffffffffu, s, o);
            ss += __shfl_xor_sync(0xffffffffu, ss, o);
        }
        const float mean = s * (1.f / 96.f);
        const float var  = ss * (1.f / 96.f) - mean * mean;
        const float rstd = rsqrtf(var + 1e-5f);
        sxn[t][lane]      = (v0 - mean) * rstd * n2g[lane]      + n2b[lane];
        sxn[t][lane + 32] = (v1 - mean) * rstd * n2g[lane + 32] + n2b[lane + 32];
        sxn[t][lane + 64] = (v2 - mean) * rstd * n2g[lane + 64] + n2b[lane + 64];
    }
    __syncthreads();

    const int rg = tid / 16;
    const int cg = tid % 16;

    for (int ct = 0; ct < 8; ct++) {
        for (int idx = tid; idx < 48 * 24; idx += 256) {
            const int c = idx / 24, kc = idx % 24;
            *(float4*)&swt[c][kc * 4] =
                *(const float4*)&f1w[(ct * 48 + c) * C_ + kc * 4];
        }
        __syncthreads();

        float acc[4][3];
        #pragma unroll
        for (int r = 0; r < 4; r++)
            #pragma unroll
            for (int c = 0; c < 3; c++) acc[r][c] = 0.f;

        #pragma unroll 3
        for (int kc = 0; kc < 24; kc++) {
            float4 w0 = *(const float4*)&swt[cg * 3 + 0][kc * 4];
            float4 w1 = *(const float4*)&swt[cg * 3 + 1][kc * 4];
            float4 w2 = *(const float4*)&swt[cg * 3 + 2][kc * 4];
            #pragma unroll
            for (int r = 0; r < 4; r++) {
                float4 a = *(const float4*)&sxn[rg * 4 + r][kc * 4];
                acc[r][0] += a.x * w0.x + a.y * w0.y + a.z * w0.z + a.w * w0.w;
                acc[r][1] += a.x * w1.x + a.y * w1.y + a.z * w1.z + a.w * w1.w;
                acc[r][2] += a.x * w2.x + a.y * w2.y + a.z * w2.z + a.w * w2.w;
            }
        }

        #pragma unroll
        for (int c = 0; c < 3; c++) {
            const int col = ct * 48 + cg * 3 + c;
            const float bb = f1b[col];
            #pragma unroll
            for (int r = 0; r < 4; r++) {
                float v = acc[r][c] + bb;
                v = 0.5f * v * (1.f + erff(v * 0.70710678118654752f));
                g_h[(size_t)(t0 + rg * 4 + r) * HID_ + col] = v;
            }
        }
        __syncthreads();
    }
}

// ---------------------------------------------------------------------------
// K4b: FC2 (TOKx384 @ 384x96) + residual. 64 tokens/block, 256 threads.
// 4 k-slices of 96, 2 col-tiles of 48. rg=tid/16 (4 rows), cg=tid%16 (3 cols).
// smem: sh 64*96*4=24576 + swt 19200 = 43776 B
// ---------------------------------------------------------------------------
__global__ __launch_bounds__(256) void k4b_fc2(
    const float* __restrict__ f2w, const float* __restrict__ f2b,
    float* __restrict__ out)
{
    __shared__ float sh[64][C_];
    __shared__ float swt[48][PAD_];
    const int t0 = blockIdx.x * 64;
    const int tid = threadIdx.x;

    const int rg = tid / 16;
    const int cg = tid % 16;

    float acc[4][6];
    #pragma unroll
    for (int r = 0; r < 4; r++)
        #pragma unroll
        for (int c = 0; c < 6; c++) acc[r][c] = 0.f;

    for (int kt = 0; kt < 4; kt++) {
        for (int idx = tid; idx < 64 * 24; idx += 256) {
            const int r = idx / 24, kc = idx % 24;
            *(float4*)&sh[r][kc * 4] =
                *(const float4*)&g_h[(size_t)(t0 + r) * HID_ + kt * 96 + kc * 4];
        }

        for (int ct = 0; ct < 2; ct++) {
            for (int idx = tid; idx < 48 * 24; idx += 256) {
                const int c = idx / 24, kc = idx % 24;
                *(float4*)&swt[c][kc * 4] =
                    *(const float4*)&f2w[(ct * 48 + c) * HID_ + kt * 96 + kc * 4];
            }
            __syncthreads();

            #pragma unroll 3
            for (int kc = 0; kc < 24; kc++) {
                float4 w0 = *(const float4*)&swt[cg * 3 + 0][kc * 4];
                float4 w1 = *(const float4*)&swt[cg * 3 + 1][kc * 4];
                float4 w2 = *(const float4*)&swt[cg * 3 + 2][kc * 4];
                #pragma unroll
                for (int r = 0; r < 4; r++) {
                    float4 a = *(const float4*)&sh[rg * 4 + r][kc * 4];
                    acc[r][ct * 3 + 0] += a.x * w0.x + a.y * w0.y + a.z * w0.z + a.w * w0.w;
                    acc[r][ct * 3 + 1] += a.x * w1.x + a.y * w1.y + a.z * w1.z + a.w * w1.w;
                    acc[r][ct * 3 + 2] += a.x * w2.x + a.y * w2.y + a.z * w2.z + a.w * w2.w;
                }
            }
            __syncthreads();
        }
    }

    #pragma unroll
    for (int ct = 0; ct < 2; ct++) {
        #pragma unroll
        for (int c = 0; c < 3; c++) {
            const int col = ct * 48 + cg * 3 + c;
            const float bb = f2b[col];
            #pragma unroll
            for (int r = 0; r < 4; r++) {
                const size_t tok = (size_t)(t0 + rg * 4 + r);
                out[tok * C_ + col] = g_x1[tok * C_ + col] + acc[r][ct * 3 + c] + bb;
            }
        }
    }
}

// ---------------------------------------------------------------------------
extern "C" void kernel_launch(void* const* d_in, const int* in_sizes, int n_in,
                              void* d_out, int out_size)
{
    const float* x         = (const float*)d_in[0];
    const float* attn_mask = (const float*)d_in[1];
    const int*   rel_index = (const int*)  d_in[2];
    const float* n1g       = (const float*)d_in[3];
    const float* n1b       = (const float*)d_in[4];
    const float* qkvw      = (const float*)d_in[5];
    const float* qkvb      = (const float*)d_in[6];
    const float* pw        = (const float*)d_in[7];
    const float* pb        = (const float*)d_in[8];
    const float* relt      = (const float*)d_in[9];
    const float* n2g       = (const float*)d_in[10];
    const float* n2b       = (const float*)d_in[11];
    const float* f1w       = (const float*)d_in[12];
    const float* f1b       = (const float*)d_in[13];
    const float* f2w       = (const float*)d_in[14];
    const float* f2b       = (const float*)d_in[15];
    float* out = (float*)d_out;

    k1_ln_qkv<<<NWIN, 256>>>(x, n1g, n1b, qkvw, qkvb);
    k2_attn<<<dim3(NWIN, NH_), 64>>>(attn_mask, rel_index, relt);
    k3_proj<<<NWIN, 192>>>(x, pw, pb);
    k4a_fc1<<<TOK / 64, 256>>>(n2g, n2b, f1w, f1b);
    k4b_fc2<<<TOK / 64, 256>>>(f2w, f2b, out);
}